// round 4
// baseline (speedup 1.0000x reference)
#include <cuda_runtime.h>
#include <cuda_bf16.h>
#include <math.h>
#include <stdint.h>

#define BATCH 2
#define SEQ   2048
#define HID   1024
#define NH    16
#define HD    64
#define LOG2E 1.4426950408889634f
#define SQSCALE (0.125f * LOG2E)   // 1/sqrt(64) * log2(e), folded into Q

// ---------------------------------------------------------------------------
// Device scratch
// ---------------------------------------------------------------------------
__device__ __nv_bfloat16 g_Xhi[BATCH * SEQ * HID];
__device__ __nv_bfloat16 g_Xlo[BATCH * SEQ * HID];
__device__ __nv_bfloat16 g_Whi[3 * HID * HID];
__device__ __nv_bfloat16 g_Wlo[3 * HID * HID];
__device__ __nv_bfloat16 g_Qhi[BATCH * NH * SEQ * HD];  // [b,h,s,d]
__device__ __nv_bfloat16 g_Qlo[BATCH * NH * SEQ * HD];
__device__ __nv_bfloat16 g_Khi[BATCH * NH * SEQ * HD];  // [b,h,s,d]
__device__ __nv_bfloat16 g_Klo[BATCH * NH * SEQ * HD];
__device__ __nv_bfloat16 g_Vhi[BATCH * NH * HD * SEQ];  // [b,h,d,s]
__device__ __nv_bfloat16 g_Vlo[BATCH * NH * HD * SEQ];

// ---------------------------------------------------------------------------
// Helpers
// ---------------------------------------------------------------------------
__device__ __forceinline__ uint32_t smem_to_u32(const void* p) {
    uint32_t a;
    asm("{ .reg .u64 t; cvta.to.shared.u64 t, %1; cvt.u32.u64 %0, t; }"
        : "=r"(a) : "l"(p));
    return a;
}
__device__ __forceinline__ void ldsm4(uint32_t* r, uint32_t addr) {
    asm volatile("ldmatrix.sync.aligned.m8n8.x4.shared.b16 {%0,%1,%2,%3}, [%4];"
        : "=r"(r[0]), "=r"(r[1]), "=r"(r[2]), "=r"(r[3]) : "r"(addr));
}
__device__ __forceinline__ void mma16816(float* c, const uint32_t* a, const uint32_t* b) {
    asm volatile(
        "mma.sync.aligned.m16n8k16.row.col.f32.bf16.bf16.f32 "
        "{%0,%1,%2,%3}, {%4,%5,%6,%7}, {%8,%9}, {%0,%1,%2,%3};"
        : "+f"(c[0]), "+f"(c[1]), "+f"(c[2]), "+f"(c[3])
        : "r"(a[0]), "r"(a[1]), "r"(a[2]), "r"(a[3]), "r"(b[0]), "r"(b[1]));
}
#define CP16(dst_u32, src_ptr) \
    asm volatile("cp.async.cg.shared.global [%0], [%1], 16;" \
        :: "r"(dst_u32), "l"(src_ptr) : "memory")
#define CP_COMMIT() asm volatile("cp.async.commit_group;" ::: "memory")
#define CP_WAIT(n)  asm volatile("cp.async.wait_group %0;" :: "n"(n) : "memory")

__device__ __forceinline__ float exp2_fast(float x) {
    x = fmaxf(x, -100.0f);
    float z  = x + 12582912.0f;
    float kf = z - 12582912.0f;
    float f  = x - kf;
    int   n  = __float_as_int(z) - 0x4B400000;
    float p  = 1.3333558146428443e-3f;
    p = fmaf(p, f, 9.6181291076284772e-3f);
    p = fmaf(p, f, 5.5504108664821580e-2f);
    p = fmaf(p, f, 2.4022650695910072e-1f);
    p = fmaf(p, f, 6.9314718055994531e-1f);
    p = fmaf(p, f, 1.0f);
    return p * __int_as_float((n + 127) << 23);
}
__device__ __forceinline__ uint32_t pack_hi2(float a, float b, float& la, float& lb) {
    __nv_bfloat16 h0 = __float2bfloat16_rn(a);
    __nv_bfloat16 h1 = __float2bfloat16_rn(b);
    la = a - __bfloat162float(h0);
    lb = b - __bfloat162float(h1);
    __nv_bfloat162 h = __halves2bfloat162(h0, h1);
    return *reinterpret_cast<uint32_t*>(&h);
}
__device__ __forceinline__ uint32_t pack_bf2(float a, float b) {
    __nv_bfloat162 h = __halves2bfloat162(__float2bfloat16_rn(a), __float2bfloat16_rn(b));
    return *reinterpret_cast<uint32_t*>(&h);
}

// ---------------------------------------------------------------------------
// Kernel 1: split fp32 -> (hi, lo) bf16
// ---------------------------------------------------------------------------
__global__ __launch_bounds__(256) void split_bf16(
    const float* __restrict__ X, const float* __restrict__ Wq,
    const float* __restrict__ Wk, const float* __restrict__ Wv)
{
    const int t = blockIdx.y;
    const float* src;
    __nv_bfloat16 *dhi, *dlo;
    int n4;
    if (t == 0) { src = X; dhi = g_Xhi; dlo = g_Xlo; n4 = (BATCH * SEQ * HID) / 4; }
    else {
        src = (t == 1) ? Wq : ((t == 2) ? Wk : Wv);
        dhi = g_Whi + (size_t)(t - 1) * HID * HID;
        dlo = g_Wlo + (size_t)(t - 1) * HID * HID;
        n4  = (HID * HID) / 4;
    }
    int i = blockIdx.x * 256 + threadIdx.x;
    if (i >= n4) return;
    float4 v = reinterpret_cast<const float4*>(src)[i];
    float l0, l1, l2, l3;
    uint32_t h01 = pack_hi2(v.x, v.y, l0, l1);
    uint32_t h23 = pack_hi2(v.z, v.w, l2, l3);
    reinterpret_cast<uint32_t*>(dhi)[i * 2 + 0] = h01;
    reinterpret_cast<uint32_t*>(dhi)[i * 2 + 1] = h23;
    reinterpret_cast<uint32_t*>(dlo)[i * 2 + 0] = pack_bf2(l0, l1);
    reinterpret_cast<uint32_t*>(dlo)[i * 2 + 1] = pack_bf2(l2, l3);
}

// ---------------------------------------------------------------------------
// Kernel 2: QKV projection, 2-stage cp.async pipeline, k-chunks of 32.
// CTA 128m x 128n, 8 warps = 4(m) x 2(n).
// ---------------------------------------------------------------------------
#define PJ_T 80                    // smem row pitch bytes (32 bf16 + 16 pad)
#define PJ_STG 40960               // 4 buffers * 128 * 80
#define PJ_BYTES (2 * PJ_STG)      // 81920

__device__ __forceinline__ void pj_issue(
    char* sm, int s, int c, int m0, int n0,
    const __nv_bfloat16* Wh, const __nv_bfloat16* Wl, int tid)
{
    const int k0 = c * 32;
    #pragma unroll
    for (int t = 0; t < 8; ++t) {
        int idx = tid + t * 256;
        int buf = idx >> 9;            // 0:AHI 1:ALO 2:BHI 3:BLO
        int w   = idx & 511;
        int row = w >> 2, seg = w & 3;
        uint32_t so = smem_to_u32(sm) + s * PJ_STG + buf * 10240 + row * PJ_T + seg * 16;
        const __nv_bfloat16* g;
        if (buf == 0)      g = g_Xhi + (size_t)(m0 + row) * HID + k0 + seg * 8;
        else if (buf == 1) g = g_Xlo + (size_t)(m0 + row) * HID + k0 + seg * 8;
        else if (buf == 2) g = Wh + (size_t)(n0 + row) * HID + k0 + seg * 8;
        else               g = Wl + (size_t)(n0 + row) * HID + k0 + seg * 8;
        CP16(so, g);
    }
}

__global__ __launch_bounds__(256) void qkv_proj(
    const float* __restrict__ bq, const float* __restrict__ bv)
{
    extern __shared__ char sm[];
    const uint32_t sb = smem_to_u32(sm);
    const int tid = threadIdx.x, lane = tid & 31, wid = tid >> 5;
    const int wm = wid & 3, wn = wid >> 2;
    const int sel = blockIdx.z;
    const int n0 = blockIdx.x * 128, m0 = blockIdx.y * 128;
    const __nv_bfloat16* __restrict__ Wh = g_Whi + (size_t)sel * HID * HID;
    const __nv_bfloat16* __restrict__ Wl = g_Wlo + (size_t)sel * HID * HID;

    const int a_row = (lane & 7) + ((lane >> 3) & 1) * 8;
    const int a_off = (lane >> 4) * 16;           // byte offset of k-half
    const int b_row = (lane & 7) + ((lane >> 4) & 1) * 8;
    const int b_off = ((lane >> 3) & 1) * 16;

    pj_issue(sm, 0, 0, m0, n0, Wh, Wl, tid); CP_COMMIT();
    pj_issue(sm, 1, 1, m0, n0, Wh, Wl, tid); CP_COMMIT();

    float acc[2][8][4] = {};

    for (int c = 0; c < 32; ++c) {
        const int s = c & 1;
        CP_WAIT(1);
        __syncthreads();
        const uint32_t stg = sb + s * PJ_STG;
        #pragma unroll
        for (int kk = 0; kk < 2; ++kk) {
            uint32_t ah[2][4], al[2][4];
            #pragma unroll
            for (int mi = 0; mi < 2; ++mi) {
                uint32_t ra = stg + (wm * 32 + mi * 16 + a_row) * PJ_T + kk * 32 + a_off;
                ldsm4(ah[mi], ra);
                ldsm4(al[mi], ra + 10240);
            }
            #pragma unroll
            for (int nj = 0; nj < 4; ++nj) {
                uint32_t bh[4], bl[4];
                uint32_t rb = stg + 20480 + (wn * 64 + nj * 16 + b_row) * PJ_T + kk * 32 + b_off;
                ldsm4(bh, rb);
                ldsm4(bl, rb + 10240);
                #pragma unroll
                for (int mi = 0; mi < 2; ++mi) {
                    mma16816(acc[mi][2 * nj],     ah[mi], bh);
                    mma16816(acc[mi][2 * nj + 1], ah[mi], bh + 2);
                    mma16816(acc[mi][2 * nj],     ah[mi], bl);
                    mma16816(acc[mi][2 * nj + 1], ah[mi], bl + 2);
                    mma16816(acc[mi][2 * nj],     al[mi], bh);
                    mma16816(acc[mi][2 * nj + 1], al[mi], bh + 2);
                }
            }
        }
        __syncthreads();
        if (c + 2 < 32) pj_issue(sm, s, c + 2, m0, n0, Wh, Wl, tid);
        CP_COMMIT();
    }

    // Epilogue: bias/scale, split to bf16 hi/lo, store flash-ready layouts
    #pragma unroll
    for (int t8 = 0; t8 < 8; ++t8) {
        const int ng = n0 + wn * 64 + t8 * 8 + 2 * (lane & 3);
        const int h = ng >> 6, d = ng & 63;
        float2 bb = make_float2(0.f, 0.f);
        if (sel == 0) bb = *reinterpret_cast<const float2*>(bq + ng);
        if (sel == 2) bb = *reinterpret_cast<const float2*>(bv + ng);
        #pragma unroll
        for (int mi = 0; mi < 2; ++mi) {
            #pragma unroll
            for (int hf = 0; hf < 2; ++hf) {
                const int r = wm * 32 + mi * 16 + (lane >> 2) + hf * 8;
                const int m = m0 + r;
                const int b = m >> 11, ss = m & (SEQ - 1);
                float v0 = acc[mi][t8][hf * 2 + 0] + bb.x;
                float v1 = acc[mi][t8][hf * 2 + 1] + bb.y;
                if (sel == 0) { v0 *= SQSCALE; v1 *= SQSCALE; }
                float l0, l1;
                uint32_t hp = pack_hi2(v0, v1, l0, l1);
                uint32_t lp = pack_bf2(l0, l1);
                if (sel == 2) {
                    size_t o = ((size_t)(b * NH + h) * HD + d) * SEQ + ss;
                    __nv_bfloat162 h2 = *reinterpret_cast<__nv_bfloat162*>(&hp);
                    __nv_bfloat162 l2 = *reinterpret_cast<__nv_bfloat162*>(&lp);
                    g_Vhi[o] = __low2bfloat16(h2);  g_Vhi[o + SEQ] = __high2bfloat16(h2);
                    g_Vlo[o] = __low2bfloat16(l2);  g_Vlo[o + SEQ] = __high2bfloat16(l2);
                } else {
                    size_t o = ((size_t)(b * NH + h) * SEQ + ss) * HD + d;
                    if (sel == 0) {
                        *reinterpret_cast<uint32_t*>(g_Qhi + o) = hp;
                        *reinterpret_cast<uint32_t*>(g_Qlo + o) = lp;
                    } else {
                        *reinterpret_cast<uint32_t*>(g_Khi + o) = hp;
                        *reinterpret_cast<uint32_t*>(g_Klo + o) = lp;
                    }
                }
            }
        }
    }
}

// ---------------------------------------------------------------------------
// Kernel 3: flash attention. BM=128, BN=64, 2-stage cp.async pipeline.
// 8 warps, each owns 16 q-rows. P stays in registers.
// ---------------------------------------------------------------------------
#define FQK_T 144
#define FQHI  0
#define FQLO  18432
#define FST_BASE 36864
#define FST_SZ   36864            // KHI,KLO,VHI,VLO each 64*144=9216
#define FMK_BASE (FST_BASE + 2 * FST_SZ)
#define FA_BYTES (FMK_BASE + 512)
#define FNT (SEQ / 64)

__device__ __forceinline__ void fa_issue(
    char* sm, int s, int kv0, size_t bh, int b, const float* mask, int tid)
{
    const uint32_t base = smem_to_u32(sm) + FST_BASE + s * FST_SZ;
    #pragma unroll
    for (int t = 0; t < 8; ++t) {
        int idx = tid + t * 256;
        int buf = idx >> 9;
        int w   = idx & 511;
        int row = w >> 3, seg = w & 7;
        uint32_t so = base + buf * 9216 + row * FQK_T + seg * 16;
        const __nv_bfloat16* g;
        if (buf == 0)      g = g_Khi + (bh * SEQ + kv0 + row) * HD + seg * 8;
        else if (buf == 1) g = g_Klo + (bh * SEQ + kv0 + row) * HD + seg * 8;
        else if (buf == 2) g = g_Vhi + (bh * HD + row) * SEQ + kv0 + seg * 8;
        else               g = g_Vlo + (bh * HD + row) * SEQ + kv0 + seg * 8;
        CP16(so, g);
    }
    if (tid < 16) {
        uint32_t so = smem_to_u32(sm) + FMK_BASE + s * 256 + tid * 16;
        CP16(so, mask + (size_t)b * SEQ + kv0 + tid * 4);
    }
}

__global__ __launch_bounds__(256) void flash(
    const float* __restrict__ mask, float* __restrict__ out)
{
    extern __shared__ char sm[];
    const uint32_t sb = smem_to_u32(sm);
    const int tid = threadIdx.x, lane = tid & 31, wid = tid >> 5;
    const int q0 = blockIdx.x * 128, h = blockIdx.y, b = blockIdx.z;
    const size_t bh = (size_t)b * NH + h;

    const int a_row = (lane & 7) + ((lane >> 3) & 1) * 8;
    const int a_off = (lane >> 4) * 16;
    const int b_row = (lane & 7) + ((lane >> 4) & 1) * 8;
    const int b_off = ((lane >> 3) & 1) * 16;

    // Q tile via cp.async (own group)
    #pragma unroll
    for (int t = 0; t < 8; ++t) {
        int idx = tid + t * 256;
        int buf = idx >> 10;
        int w   = idx & 1023;
        int row = w >> 3, seg = w & 7;
        uint32_t so = sb + (buf ? FQLO : FQHI) + row * FQK_T + seg * 16;
        const __nv_bfloat16* g = (buf ? g_Qlo : g_Qhi) + (bh * SEQ + q0 + row) * HD + seg * 8;
        CP16(so, g);
    }
    CP_COMMIT();
    fa_issue(sm, 0, 0,  bh, b, mask, tid); CP_COMMIT();
    fa_issue(sm, 1, 64, bh, b, mask, tid); CP_COMMIT();

    CP_WAIT(2);
    __syncthreads();
    uint32_t qh[4][4], ql[4][4];
    #pragma unroll
    for (int kk = 0; kk < 4; ++kk) {
        uint32_t ra = sb + FQHI + (wid * 16 + a_row) * FQK_T + kk * 32 + a_off;
        ldsm4(qh[kk], ra);
        ldsm4(ql[kk], ra + (FQLO - FQHI));
    }

    float ctx[8][4] = {};
    float miA = -1e30f, miB = -1e30f, liA = 0.f, liB = 0.f;

    for (int tt = 0; tt < FNT; ++tt) {
        const int s = tt & 1;
        CP_WAIT(1);
        __syncthreads();
        const uint32_t stg = sb + FST_BASE + s * FST_SZ;
        const float* mk = reinterpret_cast<const float*>(sm + FMK_BASE + s * 256);

        // ---- S = Q K^T (3-term split) ----
        float sc[8][4] = {};
        #pragma unroll
        for (int kk = 0; kk < 4; ++kk) {
            #pragma unroll
            for (int nj = 0; nj < 4; ++nj) {
                uint32_t kh[4], kl[4];
                uint32_t rb = stg + (nj * 16 + b_row) * FQK_T + kk * 32 + b_off;
                ldsm4(kh, rb);
                ldsm4(kl, rb + 9216);
                mma16816(sc[2 * nj],     qh[kk], kh);
                mma16816(sc[2 * nj + 1], qh[kk], kh + 2);
                mma16816(sc[2 * nj],     qh[kk], kl);
                mma16816(sc[2 * nj + 1], qh[kk], kl + 2);
                mma16816(sc[2 * nj],     ql[kk], kh);
                mma16816(sc[2 * nj + 1], ql[kk], kh + 2);
            }
        }

        // ---- mask + online softmax ----
        float mxA = -1e30f, mxB = -1e30f;
        #pragma unroll
        for (int t = 0; t < 8; ++t) {
            float2 mv = *reinterpret_cast<const float2*>(mk + t * 8 + 2 * (lane & 3));
            sc[t][0] = fmaf(mv.x, LOG2E, sc[t][0]);
            sc[t][1] = fmaf(mv.y, LOG2E, sc[t][1]);
            sc[t][2] = fmaf(mv.x, LOG2E, sc[t][2]);
            sc[t][3] = fmaf(mv.y, LOG2E, sc[t][3]);
            mxA = fmaxf(mxA, fmaxf(sc[t][0], sc[t][1]));
            mxB = fmaxf(mxB, fmaxf(sc[t][2], sc[t][3]));
        }
        mxA = fmaxf(mxA, __shfl_xor_sync(0xffffffffu, mxA, 1));
        mxA = fmaxf(mxA, __shfl_xor_sync(0xffffffffu, mxA, 2));
        mxB = fmaxf(mxB, __shfl_xor_sync(0xffffffffu, mxB, 1));
        mxB = fmaxf(mxB, __shfl_xor_sync(0xffffffffu, mxB, 2));
        float nmA = fmaxf(miA, mxA), nmB = fmaxf(miB, mxB);
        float corrA = exp2_fast(miA - nmA), corrB = exp2_fast(miB - nmB);
        miA = nmA; miB = nmB;
        float sA = 0.f, sB = 0.f;
        #pragma unroll
        for (int t = 0; t < 8; ++t) {
            sc[t][0] = exp2_fast(sc[t][0] - nmA);
            sc[t][1] = exp2_fast(sc[t][1] - nmA);
            sc[t][2] = exp2_fast(sc[t][2] - nmB);
            sc[t][3] = exp2_fast(sc[t][3] - nmB);
            sA += sc[t][0] + sc[t][1];
            sB += sc[t][2] + sc[t][3];
        }
        sA += __shfl_xor_sync(0xffffffffu, sA, 1);
        sA += __shfl_xor_sync(0xffffffffu, sA, 2);
        sB += __shfl_xor_sync(0xffffffffu, sB, 1);
        sB += __shfl_xor_sync(0xffffffffu, sB, 2);
        liA = liA * corrA + sA;
        liB = liB * corrB + sB;
        #pragma unroll
        for (int t = 0; t < 8; ++t) {
            ctx[t][0] *= corrA; ctx[t][1] *= corrA;
            ctx[t][2] *= corrB; ctx[t][3] *= corrB;
        }

        // ---- ctx += P V ----
        #pragma unroll
        for (int j = 0; j < 4; ++j) {
            uint32_t ph[4], pl[4];
            #pragma unroll
            for (int u = 0; u < 2; ++u) {
                float l0, l1, l2, l3;
                ph[2 * u + 0] = pack_hi2(sc[2 * j + u][0], sc[2 * j + u][1], l0, l1);
                ph[2 * u + 1] = pack_hi2(sc[2 * j + u][2], sc[2 * j + u][3], l2, l3);
                pl[2 * u + 0] = pack_bf2(l0, l1);
                pl[2 * u + 1] = pack_bf2(l2, l3);
            }
            #pragma unroll
            for (int dn = 0; dn < 4; ++dn) {
                uint32_t vh[4], vl[4];
                uint32_t rb = stg + 18432 + (dn * 16 + b_row) * FQK_T + j * 32 + b_off;
                ldsm4(vh, rb);
                ldsm4(vl, rb + 9216);
                mma16816(ctx[2 * dn],     ph, vh);
                mma16816(ctx[2 * dn + 1], ph, vh + 2);
                mma16816(ctx[2 * dn],     ph, vl);
                mma16816(ctx[2 * dn + 1], ph, vl + 2);
                mma16816(ctx[2 * dn],     pl, vh);
                mma16816(ctx[2 * dn + 1], pl, vh + 2);
            }
        }
        __syncthreads();
        if (tt + 2 < FNT) fa_issue(sm, s, (tt + 2) * 64, bh, b, mask, tid);
        CP_COMMIT();
    }

    // Epilogue
    const float invA = 1.0f / liA, invB = 1.0f / liB;
    const int rA = q0 + wid * 16 + (lane >> 2);
    #pragma unroll
    for (int t = 0; t < 8; ++t) {
        const int col = h * HD + t * 8 + 2 * (lane & 3);
        float2 oA = make_float2(ctx[t][0] * invA, ctx[t][1] * invA);
        float2 oB = make_float2(ctx[t][2] * invB, ctx[t][3] * invB);
        *reinterpret_cast<float2*>(out + ((size_t)b * SEQ + rA) * HID + col)     = oA;
        *reinterpret_cast<float2*>(out + ((size_t)b * SEQ + rA + 8) * HID + col) = oB;
    }
}

// ---------------------------------------------------------------------------
// Launch
// ---------------------------------------------------------------------------
extern "C" void kernel_launch(void* const* d_in, const int* in_sizes, int n_in,
                              void* d_out, int out_size)
{
    const float* hs   = (const float*)d_in[0];
    const float* mask = (const float*)d_in[1];
    const float* Wq   = (const float*)d_in[2];
    const float* bq   = (const float*)d_in[3];
    const float* Wk   = (const float*)d_in[4];
    const float* Wv   = (const float*)d_in[5];
    const float* bv   = (const float*)d_in[6];
    float* out = (float*)d_out;

    dim3 gs((BATCH * SEQ * HID / 4 + 255) / 256, 4);
    split_bf16<<<gs, 256>>>(hs, Wq, Wk, Wv);

    cudaFuncSetAttribute(qkv_proj, cudaFuncAttributeMaxDynamicSharedMemorySize, PJ_BYTES);
    qkv_proj<<<dim3(8, 32, 3), 256, PJ_BYTES>>>(bq, bv);

    cudaFuncSetAttribute(flash, cudaFuncAttributeMaxDynamicSharedMemorySize, FA_BYTES);
    flash<<<dim3(SEQ / 128, NH, BATCH), 256, FA_BYTES>>>(mask, out);
}

// round 5
// speedup vs baseline: 1.6382x; 1.6382x over previous
#include <cuda_runtime.h>
#include <cuda_fp16.h>
#include <math.h>
#include <stdint.h>

#define BATCH 2
#define SEQ   2048
#define HID   1024
#define NH    16
#define HD    64
#define LOG2E 1.4426950408889634f
#define SQSCALE (0.125f * LOG2E)

// ---------------------------------------------------------------------------
// Device scratch
// ---------------------------------------------------------------------------
__device__ __half g_Xh[BATCH * SEQ * HID];
__device__ __half g_Wh[3 * HID * HID];
__device__ __half g_Wl[3 * HID * HID];
__device__ __half g_Qh[BATCH * NH * SEQ * HD];   // [b,h,s,d]
__device__ __half g_Kh[BATCH * NH * SEQ * HD];   // [b,h,s,d]
__device__ __half g_Kl[BATCH * NH * SEQ * HD];
__device__ __half g_Vh[BATCH * NH * HD * SEQ];   // [b,h,d,s]
__device__ __half g_Vl[BATCH * NH * HD * SEQ];

// ---------------------------------------------------------------------------
// Helpers
// ---------------------------------------------------------------------------
__device__ __forceinline__ uint32_t smem_to_u32(const void* p) {
    uint32_t a;
    asm("{ .reg .u64 t; cvta.to.shared.u64 t, %1; cvt.u32.u64 %0, t; }"
        : "=r"(a) : "l"(p));
    return a;
}
__device__ __forceinline__ void ldsm4(uint32_t* r, uint32_t addr) {
    asm volatile("ldmatrix.sync.aligned.m8n8.x4.shared.b16 {%0,%1,%2,%3}, [%4];"
        : "=r"(r[0]), "=r"(r[1]), "=r"(r[2]), "=r"(r[3]) : "r"(addr));
}
__device__ __forceinline__ void mma16816(float* c, const uint32_t* a, const uint32_t* b) {
    asm volatile(
        "mma.sync.aligned.m16n8k16.row.col.f32.f16.f16.f32 "
        "{%0,%1,%2,%3}, {%4,%5,%6,%7}, {%8,%9}, {%0,%1,%2,%3};"
        : "+f"(c[0]), "+f"(c[1]), "+f"(c[2]), "+f"(c[3])
        : "r"(a[0]), "r"(a[1]), "r"(a[2]), "r"(a[3]), "r"(b[0]), "r"(b[1]));
}
#define CP16(dst_u32, src_ptr) \
    asm volatile("cp.async.cg.shared.global [%0], [%1], 16;" \
        :: "r"(dst_u32), "l"(src_ptr) : "memory")
#define CP_COMMIT() asm volatile("cp.async.commit_group;" ::: "memory")
#define CP_WAIT(n)  asm volatile("cp.async.wait_group %0;" :: "n"(n) : "memory")

__device__ __forceinline__ float exp2_fast(float x) {
    x = fmaxf(x, -100.0f);
    float z  = x + 12582912.0f;
    float kf = z - 12582912.0f;
    float f  = x - kf;
    int   n  = __float_as_int(z) - 0x4B400000;
    float p  = 1.3333558146428443e-3f;
    p = fmaf(p, f, 9.6181291076284772e-3f);
    p = fmaf(p, f, 5.5504108664821580e-2f);
    p = fmaf(p, f, 2.4022650695910072e-1f);
    p = fmaf(p, f, 6.9314718055994531e-1f);
    p = fmaf(p, f, 1.0f);
    return p * __int_as_float((n + 127) << 23);
}
__device__ __forceinline__ uint32_t ph2(float a, float b) {
    __half2 h = __floats2half2_rn(a, b);
    return *reinterpret_cast<uint32_t*>(&h);
}
__device__ __forceinline__ uint32_t ph2_split(float a, float b, float& la, float& lb) {
    __half ha = __float2half_rn(a), hb = __float2half_rn(b);
    la = a - __half2float(ha);
    lb = b - __half2float(hb);
    __half2 h = __halves2half2(ha, hb);
    return *reinterpret_cast<uint32_t*>(&h);
}

// ---------------------------------------------------------------------------
// Kernel 1: X -> fp16 (hi only); W -> fp16 hi/lo split
// ---------------------------------------------------------------------------
__global__ __launch_bounds__(256) void split_fp16(
    const float* __restrict__ X, const float* __restrict__ Wq,
    const float* __restrict__ Wk, const float* __restrict__ Wv)
{
    const int t = blockIdx.y;
    int i = blockIdx.x * 256 + threadIdx.x;
    if (t == 0) {
        const int n4 = (BATCH * SEQ * HID) / 4;
        if (i >= n4) return;
        float4 v = reinterpret_cast<const float4*>(X)[i];
        reinterpret_cast<uint32_t*>(g_Xh)[i * 2 + 0] = ph2(v.x, v.y);
        reinterpret_cast<uint32_t*>(g_Xh)[i * 2 + 1] = ph2(v.z, v.w);
    } else {
        const int n4 = (HID * HID) / 4;
        if (i >= n4) return;
        const float* src = (t == 1) ? Wq : ((t == 2) ? Wk : Wv);
        __half* dh = g_Wh + (size_t)(t - 1) * HID * HID;
        __half* dl = g_Wl + (size_t)(t - 1) * HID * HID;
        float4 v = reinterpret_cast<const float4*>(src)[i];
        float l0, l1, l2, l3;
        uint32_t h01 = ph2_split(v.x, v.y, l0, l1);
        uint32_t h23 = ph2_split(v.z, v.w, l2, l3);
        reinterpret_cast<uint32_t*>(dh)[i * 2 + 0] = h01;
        reinterpret_cast<uint32_t*>(dh)[i * 2 + 1] = h23;
        reinterpret_cast<uint32_t*>(dl)[i * 2 + 0] = ph2(l0, l1);
        reinterpret_cast<uint32_t*>(dl)[i * 2 + 1] = ph2(l2, l3);
    }
}

// ---------------------------------------------------------------------------
// Kernel 2: QKV projection. CTA 128m x 128n, k-chunks 64, 2-stage cp.async.
// 2-term fp16 split: X_hi*(W_hi + W_lo). 8 warps = 4(m) x 2(n).
// ---------------------------------------------------------------------------
#define PJ_T 144
#define PJ_BUF 18432               // 128 * 144
#define PJ_STG (3 * PJ_BUF)        // AH, BH, BL
#define PJ_BYTES (2 * PJ_STG)      // 110592

__device__ __forceinline__ void pj_issue(
    uint32_t sb, int s, int c, int m0, int n0,
    const __half* Wh, const __half* Wl, int tid)
{
    const int k0 = c * 64;
    #pragma unroll
    for (int t = 0; t < 12; ++t) {
        int idx = tid + t * 256;
        int buf = idx >> 10;           // 0:AH 1:BH 2:BL
        int w   = idx & 1023;
        int row = w >> 3, seg = w & 7;
        uint32_t so = sb + s * PJ_STG + buf * PJ_BUF + row * PJ_T + seg * 16;
        const __half* g;
        if (buf == 0)      g = g_Xh + (size_t)(m0 + row) * HID + k0 + seg * 8;
        else if (buf == 1) g = Wh + (size_t)(n0 + row) * HID + k0 + seg * 8;
        else               g = Wl + (size_t)(n0 + row) * HID + k0 + seg * 8;
        CP16(so, g);
    }
}

__global__ __launch_bounds__(256) void qkv_proj(
    const float* __restrict__ bq, const float* __restrict__ bv)
{
    extern __shared__ char sm[];
    const uint32_t sb = smem_to_u32(sm);
    const int tid = threadIdx.x, lane = tid & 31, wid = tid >> 5;
    const int wm = wid & 3, wn = wid >> 2;
    const int sel = blockIdx.z;
    const int n0 = blockIdx.x * 128, m0 = blockIdx.y * 128;
    const __half* __restrict__ Wh = g_Wh + (size_t)sel * HID * HID;
    const __half* __restrict__ Wl = g_Wl + (size_t)sel * HID * HID;

    const int a_row = (lane & 7) + ((lane >> 3) & 1) * 8;
    const int a_off = (lane >> 4) * 16;
    const int b_row = (lane & 7) + ((lane >> 4) & 1) * 8;
    const int b_off = ((lane >> 3) & 1) * 16;

    pj_issue(sb, 0, 0, m0, n0, Wh, Wl, tid); CP_COMMIT();
    pj_issue(sb, 1, 1, m0, n0, Wh, Wl, tid); CP_COMMIT();

    float acc[2][8][4] = {};

    for (int c = 0; c < 16; ++c) {
        const int s = c & 1;
        CP_WAIT(1);
        __syncthreads();
        const uint32_t stg = sb + s * PJ_STG;
        #pragma unroll
        for (int kk = 0; kk < 4; ++kk) {
            uint32_t ah[2][4];
            #pragma unroll
            for (int mi = 0; mi < 2; ++mi) {
                uint32_t ra = stg + (wm * 32 + mi * 16 + a_row) * PJ_T + kk * 32 + a_off;
                ldsm4(ah[mi], ra);
            }
            #pragma unroll
            for (int nj = 0; nj < 4; ++nj) {
                uint32_t bh[4], bl[4];
                uint32_t rb = stg + PJ_BUF + (wn * 64 + nj * 16 + b_row) * PJ_T + kk * 32 + b_off;
                ldsm4(bh, rb);
                ldsm4(bl, rb + PJ_BUF);
                #pragma unroll
                for (int mi = 0; mi < 2; ++mi) {
                    mma16816(acc[mi][2 * nj],     ah[mi], bh);
                    mma16816(acc[mi][2 * nj + 1], ah[mi], bh + 2);
                    mma16816(acc[mi][2 * nj],     ah[mi], bl);
                    mma16816(acc[mi][2 * nj + 1], ah[mi], bl + 2);
                }
            }
        }
        __syncthreads();
        if (c + 2 < 16) pj_issue(sb, s, c + 2, m0, n0, Wh, Wl, tid);
        CP_COMMIT();
    }

    // Epilogue: bias/scale, store flash-ready fp16
    #pragma unroll
    for (int t8 = 0; t8 < 8; ++t8) {
        const int ng = n0 + wn * 64 + t8 * 8 + 2 * (lane & 3);
        const int h = ng >> 6, d = ng & 63;
        float2 bb = make_float2(0.f, 0.f);
        if (sel == 0) bb = *reinterpret_cast<const float2*>(bq + ng);
        if (sel == 2) bb = *reinterpret_cast<const float2*>(bv + ng);
        #pragma unroll
        for (int mi = 0; mi < 2; ++mi) {
            #pragma unroll
            for (int hf = 0; hf < 2; ++hf) {
                const int r = wm * 32 + mi * 16 + (lane >> 2) + hf * 8;
                const int m = m0 + r;
                const int b = m >> 11, ss = m & (SEQ - 1);
                float v0 = acc[mi][t8][hf * 2 + 0] + bb.x;
                float v1 = acc[mi][t8][hf * 2 + 1] + bb.y;
                if (sel == 0) {
                    v0 *= SQSCALE; v1 *= SQSCALE;
                    size_t o = ((size_t)(b * NH + h) * SEQ + ss) * HD + d;
                    *reinterpret_cast<uint32_t*>(g_Qh + o) = ph2(v0, v1);
                } else if (sel == 1) {
                    float l0, l1;
                    uint32_t hp = ph2_split(v0, v1, l0, l1);
                    size_t o = ((size_t)(b * NH + h) * SEQ + ss) * HD + d;
                    *reinterpret_cast<uint32_t*>(g_Kh + o) = hp;
                    *reinterpret_cast<uint32_t*>(g_Kl + o) = ph2(l0, l1);
                } else {
                    __half h0 = __float2half_rn(v0), h1 = __float2half_rn(v1);
                    float l0 = v0 - __half2float(h0), l1 = v1 - __half2float(h1);
                    size_t o = ((size_t)(b * NH + h) * HD + d) * SEQ + ss;
                    g_Vh[o] = h0;  g_Vh[o + SEQ] = h1;
                    g_Vl[o] = __float2half_rn(l0);
                    g_Vl[o + SEQ] = __float2half_rn(l1);
                }
            }
        }
    }
}

// ---------------------------------------------------------------------------
// Kernel 3: flash attention. BM=128, BN=128, 2-stage cp.async, fp16 2-term.
// ---------------------------------------------------------------------------
#define FQK_T 144
#define FV_T  272
#define FQH   0
#define FST_BASE 18432
#define FKBUF 18432               // 128*144
#define FVBUF 17408               // 64*272
#define FST_SZ (2 * FKBUF + 2 * FVBUF)   // 71680
#define FMK (FST_BASE + 2 * FST_SZ)
#define FA_BYTES (FMK + 1024)     // 162816
#define FNT (SEQ / 128)

__device__ __forceinline__ void fa_issue(
    uint32_t sb, int s, int kv0, size_t bh, int b, const float* mask, int tid)
{
    const uint32_t base = sb + FST_BASE + s * FST_SZ;
    #pragma unroll
    for (int t = 0; t < 16; ++t) {
        int idx = tid + t * 256;
        int buf = idx >> 10;
        int w   = idx & 1023;
        if (buf < 2) {
            int row = w >> 3, seg = w & 7;
            uint32_t so = base + buf * FKBUF + row * FQK_T + seg * 16;
            const __half* g = (buf ? g_Kl : g_Kh) + (bh * SEQ + kv0 + row) * HD + seg * 8;
            CP16(so, g);
        } else {
            int row = w >> 4, seg = w & 15;
            uint32_t so = base + 2 * FKBUF + (buf - 2) * FVBUF + row * FV_T + seg * 16;
            const __half* g = (buf == 2 ? g_Vh : g_Vl) + (bh * HD + row) * SEQ + kv0 + seg * 8;
            CP16(so, g);
        }
    }
    if (tid < 32) {
        uint32_t so = sb + FMK + s * 512 + tid * 16;
        CP16(so, mask + (size_t)b * SEQ + kv0 + tid * 4);
    }
}

__global__ __launch_bounds__(256) void flash(
    const float* __restrict__ mask, float* __restrict__ out)
{
    extern __shared__ char sm[];
    const uint32_t sb = smem_to_u32(sm);
    const int tid = threadIdx.x, lane = tid & 31, wid = tid >> 5;
    const int q0 = blockIdx.x * 128, h = blockIdx.y, b = blockIdx.z;
    const size_t bh = (size_t)b * NH + h;

    const int a_row = (lane & 7) + ((lane >> 3) & 1) * 8;
    const int a_off = (lane >> 4) * 16;
    const int b_row = (lane & 7) + ((lane >> 4) & 1) * 8;
    const int b_off = ((lane >> 3) & 1) * 16;

    // Q tile (hi only)
    #pragma unroll
    for (int t = 0; t < 4; ++t) {
        int idx = tid + t * 256;
        int row = idx >> 3, seg = idx & 7;
        uint32_t so = sb + FQH + row * FQK_T + seg * 16;
        CP16(so, g_Qh + (bh * SEQ + q0 + row) * HD + seg * 8);
    }
    CP_COMMIT();
    fa_issue(sb, 0, 0,   bh, b, mask, tid); CP_COMMIT();
    fa_issue(sb, 1, 128, bh, b, mask, tid); CP_COMMIT();

    CP_WAIT(2);
    __syncthreads();
    uint32_t qh[4][4];
    #pragma unroll
    for (int kk = 0; kk < 4; ++kk)
        ldsm4(qh[kk], sb + FQH + (wid * 16 + a_row) * FQK_T + kk * 32 + a_off);

    float ctx[8][4] = {};
    float miA = -1e30f, miB = -1e30f, liA = 0.f, liB = 0.f;

    for (int tt = 0; tt < FNT; ++tt) {
        const int s = tt & 1;
        CP_WAIT(1);
        __syncthreads();
        const uint32_t stg = sb + FST_BASE + s * FST_SZ;
        const float* mk = reinterpret_cast<const float*>(sm + FMK + s * 512);

        // ---- S = Q K^T : Q_hi*(K_hi + K_lo) ----
        float sc[16][4] = {};
        #pragma unroll
        for (int kk = 0; kk < 4; ++kk) {
            #pragma unroll
            for (int nj = 0; nj < 8; ++nj) {
                uint32_t kh[4], kl[4];
                uint32_t rb = stg + (nj * 16 + b_row) * FQK_T + kk * 32 + b_off;
                ldsm4(kh, rb);
                ldsm4(kl, rb + FKBUF);
                mma16816(sc[2 * nj],     qh[kk], kh);
                mma16816(sc[2 * nj + 1], qh[kk], kh + 2);
                mma16816(sc[2 * nj],     qh[kk], kl);
                mma16816(sc[2 * nj + 1], qh[kk], kl + 2);
            }
        }

        // ---- mask + online softmax (log2 domain) ----
        float mxA = -1e30f, mxB = -1e30f;
        #pragma unroll
        for (int t = 0; t < 16; ++t) {
            float2 mv = *reinterpret_cast<const float2*>(mk + t * 8 + 2 * (lane & 3));
            sc[t][0] = fmaf(mv.x, LOG2E, sc[t][0]);
            sc[t][1] = fmaf(mv.y, LOG2E, sc[t][1]);
            sc[t][2] = fmaf(mv.x, LOG2E, sc[t][2]);
            sc[t][3] = fmaf(mv.y, LOG2E, sc[t][3]);
            mxA = fmaxf(mxA, fmaxf(sc[t][0], sc[t][1]));
            mxB = fmaxf(mxB, fmaxf(sc[t][2], sc[t][3]));
        }
        mxA = fmaxf(mxA, __shfl_xor_sync(0xffffffffu, mxA, 1));
        mxA = fmaxf(mxA, __shfl_xor_sync(0xffffffffu, mxA, 2));
        mxB = fmaxf(mxB, __shfl_xor_sync(0xffffffffu, mxB, 1));
        mxB = fmaxf(mxB, __shfl_xor_sync(0xffffffffu, mxB, 2));
        float nmA = fmaxf(miA, mxA), nmB = fmaxf(miB, mxB);
        float corrA = exp2_fast(miA - nmA), corrB = exp2_fast(miB - nmB);
        miA = nmA; miB = nmB;
        float sA = 0.f, sB = 0.f;
        #pragma unroll
        for (int t = 0; t < 16; ++t) {
            sc[t][0] = exp2_fast(sc[t][0] - nmA);
            sc[t][1] = exp2_fast(sc[t][1] - nmA);
            sc[t][2] = exp2_fast(sc[t][2] - nmB);
            sc[t][3] = exp2_fast(sc[t][3] - nmB);
            sA += sc[t][0] + sc[t][1];
            sB += sc[t][2] + sc[t][3];
        }
        sA += __shfl_xor_sync(0xffffffffu, sA, 1);
        sA += __shfl_xor_sync(0xffffffffu, sA, 2);
        sB += __shfl_xor_sync(0xffffffffu, sB, 1);
        sB += __shfl_xor_sync(0xffffffffu, sB, 2);
        liA = liA * corrA + sA;
        liB = liB * corrB + sB;
        #pragma unroll
        for (int t = 0; t < 8; ++t) {
            ctx[t][0] *= corrA; ctx[t][1] *= corrA;
            ctx[t][2] *= corrB; ctx[t][3] *= corrB;
        }

        // ---- ctx += P V : P_fp16*(V_hi + V_lo) ----
        #pragma unroll
        for (int j = 0; j < 8; ++j) {
            uint32_t ph[4];
            ph[0] = ph2(sc[2 * j][0],     sc[2 * j][1]);
            ph[1] = ph2(sc[2 * j][2],     sc[2 * j][3]);
            ph[2] = ph2(sc[2 * j + 1][0], sc[2 * j + 1][1]);
            ph[3] = ph2(sc[2 * j + 1][2], sc[2 * j + 1][3]);
            #pragma unroll
            for (int dn = 0; dn < 4; ++dn) {
                uint32_t vh[4], vl[4];
                uint32_t rb = stg + 2 * FKBUF + (dn * 16 + b_row) * FV_T + j * 32 + b_off;
                ldsm4(vh, rb);
                ldsm4(vl, rb + FVBUF);
                mma16816(ctx[2 * dn],     ph, vh);
                mma16816(ctx[2 * dn + 1], ph, vh + 2);
                mma16816(ctx[2 * dn],     ph, vl);
                mma16816(ctx[2 * dn + 1], ph, vl + 2);
            }
        }
        __syncthreads();
        if (tt + 2 < FNT) fa_issue(sb, s, (tt + 2) * 128, bh, b, mask, tid);
        CP_COMMIT();
    }

    // Epilogue
    const float invA = 1.0f / liA, invB = 1.0f / liB;
    const int rA = q0 + wid * 16 + (lane >> 2);
    #pragma unroll
    for (int t = 0; t < 8; ++t) {
        const int col = h * HD + t * 8 + 2 * (lane & 3);
        float2 oA = make_float2(ctx[t][0] * invA, ctx[t][1] * invA);
        float2 oB = make_float2(ctx[t][2] * invB, ctx[t][3] * invB);
        *reinterpret_cast<float2*>(out + ((size_t)b * SEQ + rA) * HID + col)     = oA;
        *reinterpret_cast<float2*>(out + ((size_t)b * SEQ + rA + 8) * HID + col) = oB;
    }
}

// ---------------------------------------------------------------------------
// Launch
// ---------------------------------------------------------------------------
extern "C" void kernel_launch(void* const* d_in, const int* in_sizes, int n_in,
                              void* d_out, int out_size)
{
    const float* hs   = (const float*)d_in[0];
    const float* mask = (const float*)d_in[1];
    const float* Wq   = (const float*)d_in[2];
    const float* bq   = (const float*)d_in[3];
    const float* Wk   = (const float*)d_in[4];
    const float* Wv   = (const float*)d_in[5];
    const float* bv   = (const float*)d_in[6];
    float* out = (float*)d_out;

    dim3 gs((BATCH * SEQ * HID / 4 + 255) / 256, 4);
    split_fp16<<<gs, 256>>>(hs, Wq, Wk, Wv);

    cudaFuncSetAttribute(qkv_proj, cudaFuncAttributeMaxDynamicSharedMemorySize, PJ_BYTES);
    qkv_proj<<<dim3(8, 32, 3), 256, PJ_BYTES>>>(bq, bv);

    cudaFuncSetAttribute(flash, cudaFuncAttributeMaxDynamicSharedMemorySize, FA_BYTES);
    flash<<<dim3(SEQ / 128, NH, BATCH), 256, FA_BYTES>>>(mask, out);
}

// round 6
// speedup vs baseline: 2.7943x; 1.7057x over previous
#include <cuda_runtime.h>
#include <cuda_fp16.h>
#include <math.h>
#include <stdint.h>

#define BATCH 2
#define SEQ   2048
#define HID   1024
#define NH    16
#define HD    64
#define LOG2E 1.4426950408889634f
#define SQSCALE (0.125f * LOG2E)

// ---------------------------------------------------------------------------
// Device scratch (single-precision-fp16 pipeline)
// ---------------------------------------------------------------------------
__device__ __half g_Xh[BATCH * SEQ * HID];
__device__ __half g_Wh[3 * HID * HID];
__device__ __half g_Qh[BATCH * NH * SEQ * HD];   // [b,h,s,d]
__device__ __half g_Kh[BATCH * NH * SEQ * HD];   // [b,h,s,d]
__device__ __half g_Vh[BATCH * NH * HD * SEQ];   // [b,h,d,s]

// ---------------------------------------------------------------------------
// Helpers
// ---------------------------------------------------------------------------
__device__ __forceinline__ uint32_t smem_to_u32(const void* p) {
    uint32_t a;
    asm("{ .reg .u64 t; cvta.to.shared.u64 t, %1; cvt.u32.u64 %0, t; }"
        : "=r"(a) : "l"(p));
    return a;
}
__device__ __forceinline__ void ldsm4(uint32_t* r, uint32_t addr) {
    asm volatile("ldmatrix.sync.aligned.m8n8.x4.shared.b16 {%0,%1,%2,%3}, [%4];"
        : "=r"(r[0]), "=r"(r[1]), "=r"(r[2]), "=r"(r[3]) : "r"(addr));
}
__device__ __forceinline__ void mma16816(float* c, const uint32_t* a, const uint32_t* b) {
    asm volatile(
        "mma.sync.aligned.m16n8k16.row.col.f32.f16.f16.f32 "
        "{%0,%1,%2,%3}, {%4,%5,%6,%7}, {%8,%9}, {%0,%1,%2,%3};"
        : "+f"(c[0]), "+f"(c[1]), "+f"(c[2]), "+f"(c[3])
        : "r"(a[0]), "r"(a[1]), "r"(a[2]), "r"(a[3]), "r"(b[0]), "r"(b[1]));
}
#define CP16(dst_u32, src_ptr) \
    asm volatile("cp.async.cg.shared.global [%0], [%1], 16;" \
        :: "r"(dst_u32), "l"(src_ptr) : "memory")
#define CP_COMMIT() asm volatile("cp.async.commit_group;" ::: "memory")
#define CP_WAIT(n)  asm volatile("cp.async.wait_group %0;" :: "n"(n) : "memory")

// Hardware exp2 on the MUFU pipe (log2-domain softmax).
__device__ __forceinline__ float ex2(float x) {
    float r;
    asm("ex2.approx.f32 %0, %1;" : "=f"(r) : "f"(x));
    return r;
}
__device__ __forceinline__ uint32_t ph2(float a, float b) {
    __half2 h = __floats2half2_rn(a, b);
    return *reinterpret_cast<uint32_t*>(&h);
}

// ---------------------------------------------------------------------------
// Kernel 1: fp32 -> fp16
// ---------------------------------------------------------------------------
__global__ __launch_bounds__(256) void to_fp16(
    const float* __restrict__ X, const float* __restrict__ Wq,
    const float* __restrict__ Wk, const float* __restrict__ Wv)
{
    const int t = blockIdx.y;
    int i = blockIdx.x * 256 + threadIdx.x;
    const float* src;
    __half* dst;
    int n4;
    if (t == 0) { src = X; dst = g_Xh; n4 = (BATCH * SEQ * HID) / 4; }
    else {
        src = (t == 1) ? Wq : ((t == 2) ? Wk : Wv);
        dst = g_Wh + (size_t)(t - 1) * HID * HID;
        n4  = (HID * HID) / 4;
    }
    if (i >= n4) return;
    float4 v = reinterpret_cast<const float4*>(src)[i];
    reinterpret_cast<uint32_t*>(dst)[i * 2 + 0] = ph2(v.x, v.y);
    reinterpret_cast<uint32_t*>(dst)[i * 2 + 1] = ph2(v.z, v.w);
}

// ---------------------------------------------------------------------------
// Kernel 2: QKV projection. CTA 128m x 128n, k-chunks 64, 2-stage cp.async.
// Single-term fp16. 8 warps = 4(m) x 2(n).
// ---------------------------------------------------------------------------
#define PJ_T 144
#define PJ_BUF 18432               // 128 * 144
#define PJ_STG (2 * PJ_BUF)        // AH, BH
#define PJ_BYTES (2 * PJ_STG)      // 73728

__device__ __forceinline__ void pj_issue(
    uint32_t sb, int s, int c, int m0, int n0, const __half* Wh, int tid)
{
    const int k0 = c * 64;
    #pragma unroll
    for (int t = 0; t < 8; ++t) {
        int idx = tid + t * 256;
        int buf = idx >> 10;           // 0:AH 1:BH
        int w   = idx & 1023;
        int row = w >> 3, seg = w & 7;
        uint32_t so = sb + s * PJ_STG + buf * PJ_BUF + row * PJ_T + seg * 16;
        const __half* g = buf ? (Wh + (size_t)(n0 + row) * HID + k0 + seg * 8)
                              : (g_Xh + (size_t)(m0 + row) * HID + k0 + seg * 8);
        CP16(so, g);
    }
}

__global__ __launch_bounds__(256) void qkv_proj(
    const float* __restrict__ bq, const float* __restrict__ bv)
{
    extern __shared__ char sm[];
    const uint32_t sb = smem_to_u32(sm);
    const int tid = threadIdx.x, lane = tid & 31, wid = tid >> 5;
    const int wm = wid & 3, wn = wid >> 2;
    const int sel = blockIdx.z;
    const int n0 = blockIdx.x * 128, m0 = blockIdx.y * 128;
    const __half* __restrict__ Wh = g_Wh + (size_t)sel * HID * HID;

    const int a_row = (lane & 7) + ((lane >> 3) & 1) * 8;
    const int a_off = (lane >> 4) * 16;
    const int b_row = (lane & 7) + ((lane >> 4) & 1) * 8;
    const int b_off = ((lane >> 3) & 1) * 16;

    pj_issue(sb, 0, 0, m0, n0, Wh, tid); CP_COMMIT();
    pj_issue(sb, 1, 1, m0, n0, Wh, tid); CP_COMMIT();

    float acc[2][8][4] = {};

    for (int c = 0; c < 16; ++c) {
        const int s = c & 1;
        CP_WAIT(1);
        __syncthreads();
        const uint32_t stg = sb + s * PJ_STG;
        #pragma unroll
        for (int kk = 0; kk < 4; ++kk) {
            uint32_t ah[2][4];
            #pragma unroll
            for (int mi = 0; mi < 2; ++mi)
                ldsm4(ah[mi], stg + (wm * 32 + mi * 16 + a_row) * PJ_T + kk * 32 + a_off);
            #pragma unroll
            for (int nj = 0; nj < 4; ++nj) {
                uint32_t bh[4];
                ldsm4(bh, stg + PJ_BUF + (wn * 64 + nj * 16 + b_row) * PJ_T + kk * 32 + b_off);
                #pragma unroll
                for (int mi = 0; mi < 2; ++mi) {
                    mma16816(acc[mi][2 * nj],     ah[mi], bh);
                    mma16816(acc[mi][2 * nj + 1], ah[mi], bh + 2);
                }
            }
        }
        __syncthreads();
        if (c + 2 < 16) pj_issue(sb, s, c + 2, m0, n0, Wh, tid);
        CP_COMMIT();
    }

    // Epilogue: bias/scale, store flash-ready fp16
    #pragma unroll
    for (int t8 = 0; t8 < 8; ++t8) {
        const int ng = n0 + wn * 64 + t8 * 8 + 2 * (lane & 3);
        const int h = ng >> 6, d = ng & 63;
        float2 bb = make_float2(0.f, 0.f);
        if (sel == 0) bb = *reinterpret_cast<const float2*>(bq + ng);
        if (sel == 2) bb = *reinterpret_cast<const float2*>(bv + ng);
        #pragma unroll
        for (int mi = 0; mi < 2; ++mi) {
            #pragma unroll
            for (int hf = 0; hf < 2; ++hf) {
                const int r = wm * 32 + mi * 16 + (lane >> 2) + hf * 8;
                const int m = m0 + r;
                const int b = m >> 11, ss = m & (SEQ - 1);
                float v0 = acc[mi][t8][hf * 2 + 0] + bb.x;
                float v1 = acc[mi][t8][hf * 2 + 1] + bb.y;
                if (sel == 0) {
                    v0 *= SQSCALE; v1 *= SQSCALE;
                    size_t o = ((size_t)(b * NH + h) * SEQ + ss) * HD + d;
                    *reinterpret_cast<uint32_t*>(g_Qh + o) = ph2(v0, v1);
                } else if (sel == 1) {
                    size_t o = ((size_t)(b * NH + h) * SEQ + ss) * HD + d;
                    *reinterpret_cast<uint32_t*>(g_Kh + o) = ph2(v0, v1);
                } else {
                    size_t o = ((size_t)(b * NH + h) * HD + d) * SEQ + ss;
                    g_Vh[o]       = __float2half_rn(v0);
                    g_Vh[o + SEQ] = __float2half_rn(v1);
                }
            }
        }
    }
}

// ---------------------------------------------------------------------------
// Kernel 3: flash attention. BM=128, BN=128, 2-stage cp.async, pure fp16.
// ---------------------------------------------------------------------------
#define FQK_T 144
#define FV_T  272
#define FQH   0
#define FST_BASE 18432
#define FKBUF 18432               // 128*144
#define FVBUF 17408               // 64*272
#define FST_SZ (FKBUF + FVBUF)    // 35840
#define FMK (FST_BASE + 2 * FST_SZ)
#define FA_BYTES (FMK + 1024)     // 91136
#define FNT (SEQ / 128)

__device__ __forceinline__ void fa_issue(
    uint32_t sb, int s, int kv0, size_t bh, int b, const float* mask, int tid)
{
    const uint32_t base = sb + FST_BASE + s * FST_SZ;
    #pragma unroll
    for (int t = 0; t < 8; ++t) {
        int idx = tid + t * 256;
        if (idx < 1024) {
            int row = idx >> 3, seg = idx & 7;
            CP16(base + row * FQK_T + seg * 16,
                 g_Kh + (bh * SEQ + kv0 + row) * HD + seg * 8);
        } else {
            int w = idx - 1024;
            int row = w >> 4, seg = w & 15;
            CP16(base + FKBUF + row * FV_T + seg * 16,
                 g_Vh + (bh * HD + row) * SEQ + kv0 + seg * 8);
        }
    }
    if (tid < 32) {
        CP16(sb + FMK + s * 512 + tid * 16,
             mask + (size_t)b * SEQ + kv0 + tid * 4);
    }
}

__global__ __launch_bounds__(256) void flash(
    const float* __restrict__ mask, float* __restrict__ out)
{
    extern __shared__ char sm[];
    const uint32_t sb = smem_to_u32(sm);
    const int tid = threadIdx.x, lane = tid & 31, wid = tid >> 5;
    const int q0 = blockIdx.x * 128, h = blockIdx.y, b = blockIdx.z;
    const size_t bh = (size_t)b * NH + h;

    const int a_row = (lane & 7) + ((lane >> 3) & 1) * 8;
    const int a_off = (lane >> 4) * 16;
    const int b_row = (lane & 7) + ((lane >> 4) & 1) * 8;
    const int b_off = ((lane >> 3) & 1) * 16;

    // Q tile
    #pragma unroll
    for (int t = 0; t < 4; ++t) {
        int idx = tid + t * 256;
        int row = idx >> 3, seg = idx & 7;
        CP16(sb + FQH + row * FQK_T + seg * 16,
             g_Qh + (bh * SEQ + q0 + row) * HD + seg * 8);
    }
    CP_COMMIT();
    fa_issue(sb, 0, 0,   bh, b, mask, tid); CP_COMMIT();
    fa_issue(sb, 1, 128, bh, b, mask, tid); CP_COMMIT();

    CP_WAIT(2);
    __syncthreads();
    uint32_t qh[4][4];
    #pragma unroll
    for (int kk = 0; kk < 4; ++kk)
        ldsm4(qh[kk], sb + FQH + (wid * 16 + a_row) * FQK_T + kk * 32 + a_off);

    float ctx[8][4] = {};
    float miA = -1e30f, miB = -1e30f, liA = 0.f, liB = 0.f;

    for (int tt = 0; tt < FNT; ++tt) {
        const int s = tt & 1;
        CP_WAIT(1);
        __syncthreads();
        const uint32_t stg = sb + FST_BASE + s * FST_SZ;
        const float* mk = reinterpret_cast<const float*>(sm + FMK + s * 512);

        // ---- S = Q K^T ----
        float sc[16][4] = {};
        #pragma unroll
        for (int kk = 0; kk < 4; ++kk) {
            #pragma unroll
            for (int nj = 0; nj < 8; ++nj) {
                uint32_t kh[4];
                ldsm4(kh, stg + (nj * 16 + b_row) * FQK_T + kk * 32 + b_off);
                mma16816(sc[2 * nj],     qh[kk], kh);
                mma16816(sc[2 * nj + 1], qh[kk], kh + 2);
            }
        }

        // ---- mask + online softmax (log2 domain, MUFU ex2) ----
        float mxA = -1e30f, mxB = -1e30f;
        #pragma unroll
        for (int t = 0; t < 16; ++t) {
            float2 mv = *reinterpret_cast<const float2*>(mk + t * 8 + 2 * (lane & 3));
            sc[t][0] = fmaf(mv.x, LOG2E, sc[t][0]);
            sc[t][1] = fmaf(mv.y, LOG2E, sc[t][1]);
            sc[t][2] = fmaf(mv.x, LOG2E, sc[t][2]);
            sc[t][3] = fmaf(mv.y, LOG2E, sc[t][3]);
            mxA = fmaxf(mxA, fmaxf(sc[t][0], sc[t][1]));
            mxB = fmaxf(mxB, fmaxf(sc[t][2], sc[t][3]));
        }
        mxA = fmaxf(mxA, __shfl_xor_sync(0xffffffffu, mxA, 1));
        mxA = fmaxf(mxA, __shfl_xor_sync(0xffffffffu, mxA, 2));
        mxB = fmaxf(mxB, __shfl_xor_sync(0xffffffffu, mxB, 1));
        mxB = fmaxf(mxB, __shfl_xor_sync(0xffffffffu, mxB, 2));
        float nmA = fmaxf(miA, mxA), nmB = fmaxf(miB, mxB);
        float corrA = ex2(miA - nmA), corrB = ex2(miB - nmB);
        miA = nmA; miB = nmB;
        float sA = 0.f, sB = 0.f;
        #pragma unroll
        for (int t = 0; t < 16; ++t) {
            sc[t][0] = ex2(sc[t][0] - nmA);
            sc[t][1] = ex2(sc[t][1] - nmA);
            sc[t][2] = ex2(sc[t][2] - nmB);
            sc[t][3] = ex2(sc[t][3] - nmB);
            sA += sc[t][0] + sc[t][1];
            sB += sc[t][2] + sc[t][3];
        }
        sA += __shfl_xor_sync(0xffffffffu, sA, 1);
        sA += __shfl_xor_sync(0xffffffffu, sA, 2);
        sB += __shfl_xor_sync(0xffffffffu, sB, 1);
        sB += __shfl_xor_sync(0xffffffffu, sB, 2);
        liA = liA * corrA + sA;
        liB = liB * corrB + sB;
        #pragma unroll
        for (int t = 0; t < 8; ++t) {
            ctx[t][0] *= corrA; ctx[t][1] *= corrA;
            ctx[t][2] *= corrB; ctx[t][3] *= corrB;
        }

        // ---- ctx += P V ----
        #pragma unroll
        for (int j = 0; j < 8; ++j) {
            uint32_t ph[4];
            ph[0] = ph2(sc[2 * j][0],     sc[2 * j][1]);
            ph[1] = ph2(sc[2 * j][2],     sc[2 * j][3]);
            ph[2] = ph2(sc[2 * j + 1][0], sc[2 * j + 1][1]);
            ph[3] = ph2(sc[2 * j + 1][2], sc[2 * j + 1][3]);
            #pragma unroll
            for (int dn = 0; dn < 4; ++dn) {
                uint32_t vh[4];
                ldsm4(vh, stg + FKBUF + (dn * 16 + b_row) * FV_T + j * 32 + b_off);
                mma16816(ctx[2 * dn],     ph, vh);
                mma16816(ctx[2 * dn + 1], ph, vh + 2);
            }
        }
        __syncthreads();
        if (tt + 2 < FNT) fa_issue(sb, s, (tt + 2) * 128, bh, b, mask, tid);
        CP_COMMIT();
    }

    // Epilogue
    const float invA = 1.0f / liA, invB = 1.0f / liB;
    const int rA = q0 + wid * 16 + (lane >> 2);
    #pragma unroll
    for (int t = 0; t < 8; ++t) {
        const int col = h * HD + t * 8 + 2 * (lane & 3);
        float2 oA = make_float2(ctx[t][0] * invA, ctx[t][1] * invA);
        float2 oB = make_float2(ctx[t][2] * invB, ctx[t][3] * invB);
        *reinterpret_cast<float2*>(out + ((size_t)b * SEQ + rA) * HID + col)     = oA;
        *reinterpret_cast<float2*>(out + ((size_t)b * SEQ + rA + 8) * HID + col) = oB;
    }
}

// ---------------------------------------------------------------------------
// Launch
// ---------------------------------------------------------------------------
extern "C" void kernel_launch(void* const* d_in, const int* in_sizes, int n_in,
                              void* d_out, int out_size)
{
    const float* hs   = (const float*)d_in[0];
    const float* mask = (const float*)d_in[1];
    const float* Wq   = (const float*)d_in[2];
    const float* bq   = (const float*)d_in[3];
    const float* Wk   = (const float*)d_in[4];
    const float* Wv   = (const float*)d_in[5];
    const float* bv   = (const float*)d_in[6];
    float* out = (float*)d_out;

    dim3 gs((BATCH * SEQ * HID / 4 + 255) / 256, 4);
    to_fp16<<<gs, 256>>>(hs, Wq, Wk, Wv);

    cudaFuncSetAttribute(qkv_proj, cudaFuncAttributeMaxDynamicSharedMemorySize, PJ_BYTES);
    qkv_proj<<<dim3(8, 32, 3), 256, PJ_BYTES>>>(bq, bv);

    cudaFuncSetAttribute(flash, cudaFuncAttributeMaxDynamicSharedMemorySize, FA_BYTES);
    flash<<<dim3(SEQ / 128, NH, BATCH), 256, FA_BYTES>>>(mask, out);
}